// round 1
// baseline (speedup 1.0000x reference)
#include <cuda_runtime.h>

#define B_ 512
#define T_ 256
#define C_ 384
#define H_ 64
#define SCALE_F 19.595917942265423f

// scratch for q,k,v projections: [B,T,H] each (fp32)
__device__ float g_q[B_ * T_ * H_];
__device__ float g_k[B_ * T_ * H_];
__device__ float g_v[B_ * T_ * H_];

// ---------------------------------------------------------------------------
// Projection kernel: for 64 rows of x (in smem, transposed), compute q,k,v
// tiles sequentially. CTA = 256 threads (16x16), thread tile 4x4.
// ---------------------------------------------------------------------------
#define XT_PITCH 68                       // pad: float4-aligned rows, low-conflict
#define PROJ_SMEM ((C_ * XT_PITCH + 32 * H_) * 4)

__global__ __launch_bounds__(256, 2)
void proj_kernel(const float* __restrict__ x, const float* __restrict__ Wq,
                 const float* __restrict__ Wk, const float* __restrict__ Wv) {
    extern __shared__ float sm[];
    float* xT = sm;                        // [384][68]  (xT[k][i])
    float* Wt = sm + C_ * XT_PITCH;        // [32][64]

    const int tid  = threadIdx.x;
    const int row0 = blockIdx.x * 64;

    // load x tile (64 rows x 384) transposed into smem, float4 global loads
    const float4* xg = reinterpret_cast<const float4*>(x + (size_t)row0 * C_);
    #pragma unroll
    for (int it = 0; it < 24; ++it) {
        int idx = tid + it * 256;          // float4 index, 0..6143
        float4 v = xg[idx];
        int lin = idx << 2;
        int i = lin / C_;
        int k = lin - i * C_;              // multiple of 4
        xT[(k + 0) * XT_PITCH + i] = v.x;
        xT[(k + 1) * XT_PITCH + i] = v.y;
        xT[(k + 2) * XT_PITCH + i] = v.z;
        xT[(k + 3) * XT_PITCH + i] = v.w;
    }

    const int ty = tid >> 4, tx = tid & 15;
    const int i0 = ty * 4, j0 = tx * 4;

    const float* Ws[3] = {Wq, Wk, Wv};
    float* Os[3] = {g_q, g_k, g_v};

    #pragma unroll 1
    for (int w = 0; w < 3; ++w) {
        const float* W = Ws[w];
        float acc[4][4];
        #pragma unroll
        for (int r = 0; r < 4; ++r)
            #pragma unroll
            for (int c = 0; c < 4; ++c) acc[r][c] = 0.0f;

        #pragma unroll 1
        for (int kt = 0; kt < C_ / 32; ++kt) {
            __syncthreads();               // also orders xT writes before reads
            #pragma unroll
            for (int it = 0; it < 8; ++it) {
                int idx = tid + it * 256;  // 0..2047 = 32 rows x 64 cols
                Wt[idx] = W[kt * 32 * H_ + idx];
            }
            __syncthreads();
            #pragma unroll
            for (int kk = 0; kk < 32; ++kk) {
                float4 a = *reinterpret_cast<const float4*>(&xT[(kt * 32 + kk) * XT_PITCH + i0]);
                float4 b = *reinterpret_cast<const float4*>(&Wt[kk * H_ + j0]);
                float av[4] = {a.x, a.y, a.z, a.w};
                float bv[4] = {b.x, b.y, b.z, b.w};
                #pragma unroll
                for (int r = 0; r < 4; ++r)
                    #pragma unroll
                    for (int c = 0; c < 4; ++c)
                        acc[r][c] = fmaf(av[r], bv[c], acc[r][c]);
            }
        }
        float* O = Os[w];
        #pragma unroll
        for (int r = 0; r < 4; ++r) {
            float4 o = make_float4(acc[r][0], acc[r][1], acc[r][2], acc[r][3]);
            *reinterpret_cast<float4*>(&O[(size_t)(row0 + i0 + r) * H_ + j0]) = o;
        }
    }
}

// ---------------------------------------------------------------------------
// Attention kernel: one CTA per batch. K^T and V resident in smem.
// Query blocks of 32 rows; causal skip at warp-contiguous 16-col granularity.
// ---------------------------------------------------------------------------
#define KT_PITCH 260                      // 256 + 4: float4 alignment
#define QT_PITCH 36                       // 32 + 4
#define ST_PITCH 36
#define ATTN_SMEM ((64 * KT_PITCH + T_ * H_ + 64 * QT_PITCH + T_ * ST_PITCH + 256 + 32 + 32) * 4)

__global__ __launch_bounds__(256, 1)
void attn_kernel(float* __restrict__ out) {
    extern __shared__ float sm[];
    float* Kt   = sm;                      // [64][260]  Kt[h][s]
    float* Vs   = Kt + 64 * KT_PITCH;      // [256][64]  Vs[s][h]
    float* Qt   = Vs + T_ * H_;            // [64][36]   Qt[h][i]  (pre-scaled)
    float* St   = Qt + 64 * QT_PITCH;      // [256][36]  St[s][i]
    float* red  = St + T_ * ST_PITCH;      // [8][32]
    float* rmax = red + 256;               // [32]
    float* rsum = rmax + 32;               // [32]

    const int bb  = blockIdx.x;
    const int tid = threadIdx.x;
    const float* qp = g_q + (size_t)bb * T_ * H_;
    const float* kp = g_k + (size_t)bb * T_ * H_;
    const float* vp = g_v + (size_t)bb * T_ * H_;

    // load K (transposed) and V
    #pragma unroll 4
    for (int it = 0; it < 64; ++it) {
        int idx = tid + it * 256;          // 0..16383
        int s = idx >> 6, h = idx & 63;
        Kt[h * KT_PITCH + s] = kp[idx];
        Vs[idx] = vp[idx];
    }

    // S-compute mapping: warp w owns cols [16w,16w+16) (+ group B [128+16w,..))
    const int rg  = tid & 7;               // row group -> rows i0..i0+3
    const int i0  = rg * 4;
    const int cg  = tid >> 3;               // col group (cg>>2 == warp id)
    const int cA  = cg * 4;
    const int cB  = 128 + cg * 4;
    // softmax mapping
    const int p   = tid >> 5;
    const int row = tid & 31;
    // PV mapping
    const int i0v = (tid >> 5) * 4;
    const int c0v = (tid & 31) * 2;

    #pragma unroll 1
    for (int qb = 0; qb < 8; ++qb) {
        const int ncols = 32 * (qb + 1);

        __syncthreads();                   // previous PV done with St
        // load Q tile (32 rows), pre-multiplied by SCALE
        #pragma unroll
        for (int it = 0; it < 8; ++it) {
            int idx = tid + it * 256;      // 0..2047
            int i = idx >> 6, h = idx & 63;
            Qt[h * QT_PITCH + i] = qp[(32 * qb + i) * H_ + h] * SCALE_F;
        }
        __syncthreads();

        // ---- S = Q K^T (pre-scaled) ----
        if (cA < ncols) {
            float acc[4][8];
            #pragma unroll
            for (int r = 0; r < 4; ++r)
                #pragma unroll
                for (int c = 0; c < 8; ++c) acc[r][c] = 0.0f;

            if (cB < ncols) {
                #pragma unroll 8
                for (int k = 0; k < 64; ++k) {
                    float4 a  = *reinterpret_cast<const float4*>(&Qt[k * QT_PITCH + i0]);
                    float4 b0 = *reinterpret_cast<const float4*>(&Kt[k * KT_PITCH + cA]);
                    float4 b1 = *reinterpret_cast<const float4*>(&Kt[k * KT_PITCH + cB]);
                    float av[4] = {a.x, a.y, a.z, a.w};
                    float b0v[4] = {b0.x, b0.y, b0.z, b0.w};
                    float b1v[4] = {b1.x, b1.y, b1.z, b1.w};
                    #pragma unroll
                    for (int r = 0; r < 4; ++r) {
                        #pragma unroll
                        for (int c = 0; c < 4; ++c) {
                            acc[r][c]     = fmaf(av[r], b0v[c], acc[r][c]);
                            acc[r][c + 4] = fmaf(av[r], b1v[c], acc[r][c + 4]);
                        }
                    }
                }
                #pragma unroll
                for (int c = 0; c < 4; ++c)
                    #pragma unroll
                    for (int r = 0; r < 4; ++r) {
                        St[(cA + c) * ST_PITCH + i0 + r] = acc[r][c];
                        St[(cB + c) * ST_PITCH + i0 + r] = acc[r][c + 4];
                    }
            } else {
                #pragma unroll 8
                for (int k = 0; k < 64; ++k) {
                    float4 a  = *reinterpret_cast<const float4*>(&Qt[k * QT_PITCH + i0]);
                    float4 b0 = *reinterpret_cast<const float4*>(&Kt[k * KT_PITCH + cA]);
                    float av[4] = {a.x, a.y, a.z, a.w};
                    float b0v[4] = {b0.x, b0.y, b0.z, b0.w};
                    #pragma unroll
                    for (int r = 0; r < 4; ++r)
                        #pragma unroll
                        for (int c = 0; c < 4; ++c)
                            acc[r][c] = fmaf(av[r], b0v[c], acc[r][c]);
                }
                #pragma unroll
                for (int c = 0; c < 4; ++c)
                    #pragma unroll
                    for (int r = 0; r < 4; ++r)
                        St[(cA + c) * ST_PITCH + i0 + r] = acc[r][c];
            }
        }
        __syncthreads();

        // ---- softmax (8 threads per row) ----
        const int rglob = 32 * qb + row;
        const int sbeg  = 32 * p;
        float lmax = -3.0e38f;
        if (sbeg < ncols) {
            int send = min(sbeg + 32, rglob + 1);
            for (int s = sbeg; s < send; ++s)
                lmax = fmaxf(lmax, St[s * ST_PITCH + row]);
        }
        red[p * 32 + row] = lmax;
        __syncthreads();
        if (p == 0) {
            float m = red[row];
            #pragma unroll
            for (int q = 1; q < 8; ++q) m = fmaxf(m, red[q * 32 + row]);
            rmax[row] = m;
        }
        __syncthreads();
        const float m = rmax[row];
        float lsum = 0.0f;
        if (sbeg < ncols) {
            #pragma unroll 4
            for (int s = sbeg; s < sbeg + 32; ++s) {
                float sv = St[s * ST_PITCH + row];
                float pv = (s <= rglob) ? __expf(sv - m) : 0.0f;
                St[s * ST_PITCH + row] = pv;
                lsum += pv;
            }
        }
        red[p * 32 + row] = lsum;
        __syncthreads();
        if (p == 0) {
            float ssum = red[row];
            #pragma unroll
            for (int q = 1; q < 8; ++q) ssum += red[q * 32 + row];
            rsum[row] = 1.0f / ssum;
        }
        __syncthreads();

        // ---- O = P V (normalization folded into write) ----
        float oacc[4][2];
        #pragma unroll
        for (int r = 0; r < 4; ++r) { oacc[r][0] = 0.0f; oacc[r][1] = 0.0f; }
        #pragma unroll 8
        for (int s = 0; s < ncols; ++s) {
            float4 a = *reinterpret_cast<const float4*>(&St[s * ST_PITCH + i0v]);
            float2 b = *reinterpret_cast<const float2*>(&Vs[s * H_ + c0v]);
            float av[4] = {a.x, a.y, a.z, a.w};
            #pragma unroll
            for (int r = 0; r < 4; ++r) {
                oacc[r][0] = fmaf(av[r], b.x, oacc[r][0]);
                oacc[r][1] = fmaf(av[r], b.y, oacc[r][1]);
            }
        }
        #pragma unroll
        for (int r = 0; r < 4; ++r) {
            float inv = rsum[i0v + r];
            float2 o;
            o.x = oacc[r][0] * inv;
            o.y = oacc[r][1] * inv;
            *reinterpret_cast<float2*>(
                &out[((size_t)bb * T_ + 32 * qb + i0v + r) * H_ + c0v]) = o;
        }
    }
}

// ---------------------------------------------------------------------------
extern "C" void kernel_launch(void* const* d_in, const int* in_sizes, int n_in,
                              void* d_out, int out_size) {
    const float* x  = (const float*)d_in[0];
    const float* Wq = (const float*)d_in[1];
    const float* Wk = (const float*)d_in[2];
    const float* Wv = (const float*)d_in[3];
    float* out = (float*)d_out;

    cudaFuncSetAttribute(proj_kernel, cudaFuncAttributeMaxDynamicSharedMemorySize, PROJ_SMEM);
    cudaFuncSetAttribute(attn_kernel, cudaFuncAttributeMaxDynamicSharedMemorySize, ATTN_SMEM);

    proj_kernel<<<(B_ * T_) / 64, 256, PROJ_SMEM>>>(x, Wq, Wk, Wv);
    attn_kernel<<<B_, 256, ATTN_SMEM>>>(out);
}

// round 2
// speedup vs baseline: 1.2810x; 1.2810x over previous
#include <cuda_runtime.h>

#define B_ 512
#define T_ 256
#define C_ 384
#define H_ 64
#define SCALE_F 19.595917942265423f

// scratch for q,k,v projections: [B,T,H] each (fp32)
__device__ float g_q[B_ * T_ * H_];
__device__ float g_k[B_ * T_ * H_];
__device__ float g_v[B_ * T_ * H_];

// ===========================================================================
// Projection via mma.sync m16n8k8 TF32, 3-pass split (hi*hi + hi*lo + lo*hi).
// CTA: 256 threads (8 warps, 2 warp-rows x 4 warp-cols).
// CTA tile: M=128, N=192 (q|k|v fused), K-chunks of 32, double buffered.
// smem holds (hi,lo) tf32 pairs in mma-fragment order -> conflict-free LDS.128
// ===========================================================================
#define PROJ_A_F4 2048                 // 128x32 x2(hi,lo) floats = 2048 float4
#define PROJ_B_F4 3072                 // 32x192 x2 floats = 3072 float4
#define PROJ_BUF_F4 (PROJ_A_F4 + PROJ_B_F4)   // 5120 float4 = 80 KB
#define PROJ_SMEM (2 * PROJ_BUF_F4 * 16)      // 160 KB

__device__ __forceinline__ float2 to_tf32_pair(float v) {
    unsigned hi, lo;
    asm("cvt.rna.tf32.f32 %0, %1;" : "=r"(hi) : "f"(v));
    float hif = __uint_as_float(hi);
    float r = v - hif;
    asm("cvt.rna.tf32.f32 %0, %1;" : "=r"(lo) : "f"(r));
    return make_float2(hif, __uint_as_float(lo));
}

__device__ __forceinline__ void mma_tf32(float* c,
    unsigned a0, unsigned a1, unsigned a2, unsigned a3,
    unsigned b0, unsigned b1) {
    asm("mma.sync.aligned.m16n8k8.row.col.f32.tf32.tf32.f32 "
        "{%0,%1,%2,%3},{%4,%5,%6,%7},{%8,%9},{%0,%1,%2,%3};"
        : "+f"(c[0]), "+f"(c[1]), "+f"(c[2]), "+f"(c[3])
        : "r"(a0), "r"(a1), "r"(a2), "r"(a3), "r"(b0), "r"(b1));
}

__global__ __launch_bounds__(256, 1)
void proj_mma_kernel(const float* __restrict__ x, const float* __restrict__ Wq,
                     const float* __restrict__ Wk, const float* __restrict__ Wv) {
    extern __shared__ float4 sm4[];
    const int tid  = threadIdx.x;
    const int lane = tid & 31;
    const int wid  = tid >> 5;
    const int wm   = wid >> 2;          // warp row (0..1), 64 M-rows each
    const int wn   = wid & 3;           // warp col (0..3), 48 N-cols each
    const int row0 = blockIdx.x * 128;

    const float* Ws[3] = {Wq, Wk, Wv};
    float* Os[3] = {g_q, g_k, g_v};

    // ---- loader-side constants ----
    const int lm   = tid >> 1;          // x row handled by this thread (0..127)
    const int lkof = (tid & 1) * 16;    // local-k base (0 or 16)
    // A-store constants
    const int a_tile_m  = (lm >> 4) * 4;
    const int a_comp    = (lm >> 3) & 1;
    const int a_lane_b  = (lm & 7) * 4;

    float4 xa[4];
    float4 wb[6];

    // ---------- load chunk into regs ----------
    auto load_regs = [&](int kc) {
        const float4* xg = reinterpret_cast<const float4*>(x)
                         + (size_t)(row0 + lm) * 96 + kc * 8 + (tid & 1) * 4;
        #pragma unroll
        for (int j = 0; j < 4; ++j) xa[j] = xg[j];
        #pragma unroll
        for (int w = 0; w < 3; ++w) {
            #pragma unroll
            for (int i = 0; i < 2; ++i) {
                int idx = tid * 2 + i;          // 0..511
                int k   = idx >> 4;             // 0..31
                int n4  = idx & 15;             // float4 col within matrix
                wb[w * 2 + i] = reinterpret_cast<const float4*>(Ws[w])
                                [(size_t)(kc * 32 + k) * 16 + n4];
            }
        }
    };

    // ---------- convert + store chunk to smem (fragment order) ----------
    auto store_chunk = [&](int buf) {
        float2* Af2 = reinterpret_cast<float2*>(sm4 + buf * PROJ_BUF_F4);
        float2* Bf2 = reinterpret_cast<float2*>(sm4 + buf * PROJ_BUF_F4 + PROJ_A_F4);
        #pragma unroll
        for (int j = 0; j < 4; ++j) {
            int kk    = lkof + j * 4;
            int ks    = kk >> 3;
            int chalf = (kk >> 2) & 1;
            int tile  = a_tile_m + ks;
            int base  = (tile * 64 + chalf * 32 + a_lane_b) * 2 + a_comp;
            float v[4] = {xa[j].x, xa[j].y, xa[j].z, xa[j].w};
            #pragma unroll
            for (int e = 0; e < 4; ++e)
                Af2[base + e * 2] = to_tf32_pair(v[e]);
        }
        #pragma unroll
        for (int w = 0; w < 3; ++w) {
            #pragma unroll
            for (int i = 0; i < 2; ++i) {
                int idx = tid * 2 + i;
                int k   = idx >> 4;
                int n4  = idx & 15;
                int ks   = k >> 3;
                int comp = (k >> 2) & 1;
                int rb   = k & 3;
                int ncomb = w * 64 + n4 * 4;
                int nt    = ncomb >> 3;
                int cb    = ncomb & 7;
                int base  = ((nt * 4 + ks) * 32 + cb * 4 + rb) * 2 + comp;
                float4 q = wb[w * 2 + i];
                float v[4] = {q.x, q.y, q.z, q.w};
                #pragma unroll
                for (int e = 0; e < 4; ++e)
                    Bf2[base + e * 8] = to_tf32_pair(v[e]);
            }
        }
    };

    float acc[4][6][4];
    #pragma unroll
    for (int mt = 0; mt < 4; ++mt)
        #pragma unroll
        for (int nt = 0; nt < 6; ++nt)
            #pragma unroll
            for (int e = 0; e < 4; ++e) acc[mt][nt][e] = 0.0f;

    // ---------- mma over one chunk ----------
    auto mma_chunk = [&](int buf) {
        const float4* Af4 = sm4 + buf * PROJ_BUF_F4;
        const float4* Bf4 = sm4 + buf * PROJ_BUF_F4 + PROJ_A_F4;
        #pragma unroll
        for (int ks = 0; ks < 4; ++ks) {
            float4 a0[4], a1[4];
            #pragma unroll
            for (int mt = 0; mt < 4; ++mt) {
                int t = ((wm * 4 + mt) * 4 + ks);
                a0[mt] = Af4[t * 64 + lane];
                a1[mt] = Af4[t * 64 + 32 + lane];
            }
            float4 bf[6];
            #pragma unroll
            for (int nt = 0; nt < 6; ++nt) {
                int t = ((wn * 6 + nt) * 4 + ks);
                bf[nt] = Bf4[t * 32 + lane];
            }
            #pragma unroll
            for (int mt = 0; mt < 4; ++mt) {
                unsigned ah0 = __float_as_uint(a0[mt].x);
                unsigned ah1 = __float_as_uint(a0[mt].z);
                unsigned ah2 = __float_as_uint(a1[mt].x);
                unsigned ah3 = __float_as_uint(a1[mt].z);
                unsigned al0 = __float_as_uint(a0[mt].y);
                unsigned al1 = __float_as_uint(a0[mt].w);
                unsigned al2 = __float_as_uint(a1[mt].y);
                unsigned al3 = __float_as_uint(a1[mt].w);
                #pragma unroll
                for (int nt = 0; nt < 6; ++nt) {
                    unsigned bh0 = __float_as_uint(bf[nt].x);
                    unsigned bh1 = __float_as_uint(bf[nt].z);
                    unsigned bl0 = __float_as_uint(bf[nt].y);
                    unsigned bl1 = __float_as_uint(bf[nt].w);
                    mma_tf32(acc[mt][nt], ah0, ah1, ah2, ah3, bh0, bh1);
                    mma_tf32(acc[mt][nt], ah0, ah1, ah2, ah3, bl0, bl1);
                    mma_tf32(acc[mt][nt], al0, al1, al2, al3, bh0, bh1);
                }
            }
        }
    };

    // ---------- pipeline ----------
    load_regs(0);
    store_chunk(0);
    __syncthreads();
    #pragma unroll 1
    for (int c = 0; c < 12; ++c) {
        if (c < 11) load_regs(c + 1);
        mma_chunk(c & 1);
        if (c < 11) {
            store_chunk((c + 1) & 1);
            __syncthreads();
        }
    }

    // ---------- epilogue ----------
    #pragma unroll
    for (int mt = 0; mt < 4; ++mt) {
        #pragma unroll
        for (int nt = 0; nt < 6; ++nt) {
            int ncomb = wn * 48 + nt * 8;
            int w     = ncomb >> 6;
            int col   = ncomb & 63;
            float* O  = Os[w];
            int gr = row0 + wm * 64 + mt * 16 + (lane >> 2);
            int gc = col + (lane & 3) * 2;
            float2 o01 = make_float2(acc[mt][nt][0], acc[mt][nt][1]);
            float2 o23 = make_float2(acc[mt][nt][2], acc[mt][nt][3]);
            *reinterpret_cast<float2*>(&O[(size_t)gr * 64 + gc]) = o01;
            *reinterpret_cast<float2*>(&O[(size_t)(gr + 8) * 64 + gc]) = o23;
        }
    }
}

// ---------------------------------------------------------------------------
// Attention kernel: one CTA per batch. K^T and V resident in smem.
// (unchanged from round 1 — known good)
// ---------------------------------------------------------------------------
#define KT_PITCH 260
#define QT_PITCH 36
#define ST_PITCH 36
#define ATTN_SMEM ((64 * KT_PITCH + T_ * H_ + 64 * QT_PITCH + T_ * ST_PITCH + 256 + 32 + 32) * 4)

__global__ __launch_bounds__(256, 1)
void attn_kernel(float* __restrict__ out) {
    extern __shared__ float sm[];
    float* Kt   = sm;
    float* Vs   = Kt + 64 * KT_PITCH;
    float* Qt   = Vs + T_ * H_;
    float* St   = Qt + 64 * QT_PITCH;
    float* red  = St + T_ * ST_PITCH;
    float* rmax = red + 256;
    float* rsum = rmax + 32;

    const int bb  = blockIdx.x;
    const int tid = threadIdx.x;
    const float* qp = g_q + (size_t)bb * T_ * H_;
    const float* kp = g_k + (size_t)bb * T_ * H_;
    const float* vp = g_v + (size_t)bb * T_ * H_;

    #pragma unroll 4
    for (int it = 0; it < 64; ++it) {
        int idx = tid + it * 256;
        int s = idx >> 6, h = idx & 63;
        Kt[h * KT_PITCH + s] = kp[idx];
        Vs[idx] = vp[idx];
    }

    const int rg  = tid & 7;
    const int i0  = rg * 4;
    const int cg  = tid >> 3;
    const int cA  = cg * 4;
    const int cB  = 128 + cg * 4;
    const int p   = tid >> 5;
    const int row = tid & 31;
    const int i0v = (tid >> 5) * 4;
    const int c0v = (tid & 31) * 2;

    #pragma unroll 1
    for (int qb = 0; qb < 8; ++qb) {
        const int ncols = 32 * (qb + 1);

        __syncthreads();
        #pragma unroll
        for (int it = 0; it < 8; ++it) {
            int idx = tid + it * 256;
            int i = idx >> 6, h = idx & 63;
            Qt[h * QT_PITCH + i] = qp[(32 * qb + i) * H_ + h] * SCALE_F;
        }
        __syncthreads();

        if (cA < ncols) {
            float acc[4][8];
            #pragma unroll
            for (int r = 0; r < 4; ++r)
                #pragma unroll
                for (int c = 0; c < 8; ++c) acc[r][c] = 0.0f;

            if (cB < ncols) {
                #pragma unroll 8
                for (int k = 0; k < 64; ++k) {
                    float4 a  = *reinterpret_cast<const float4*>(&Qt[k * QT_PITCH + i0]);
                    float4 b0 = *reinterpret_cast<const float4*>(&Kt[k * KT_PITCH + cA]);
                    float4 b1 = *reinterpret_cast<const float4*>(&Kt[k * KT_PITCH + cB]);
                    float av[4] = {a.x, a.y, a.z, a.w};
                    float b0v[4] = {b0.x, b0.y, b0.z, b0.w};
                    float b1v[4] = {b1.x, b1.y, b1.z, b1.w};
                    #pragma unroll
                    for (int r = 0; r < 4; ++r) {
                        #pragma unroll
                        for (int c = 0; c < 4; ++c) {
                            acc[r][c]     = fmaf(av[r], b0v[c], acc[r][c]);
                            acc[r][c + 4] = fmaf(av[r], b1v[c], acc[r][c + 4]);
                        }
                    }
                }
                #pragma unroll
                for (int c = 0; c < 4; ++c)
                    #pragma unroll
                    for (int r = 0; r < 4; ++r) {
                        St[(cA + c) * ST_PITCH + i0 + r] = acc[r][c];
                        St[(cB + c) * ST_PITCH + i0 + r] = acc[r][c + 4];
                    }
            } else {
                #pragma unroll 8
                for (int k = 0; k < 64; ++k) {
                    float4 a  = *reinterpret_cast<const float4*>(&Qt[k * QT_PITCH + i0]);
                    float4 b0 = *reinterpret_cast<const float4*>(&Kt[k * KT_PITCH + cA]);
                    float av[4] = {a.x, a.y, a.z, a.w};
                    float b0v[4] = {b0.x, b0.y, b0.z, b0.w};
                    #pragma unroll
                    for (int r = 0; r < 4; ++r)
                        #pragma unroll
                        for (int c = 0; c < 4; ++c)
                            acc[r][c] = fmaf(av[r], b0v[c], acc[r][c]);
                }
                #pragma unroll
                for (int c = 0; c < 4; ++c)
                    #pragma unroll
                    for (int r = 0; r < 4; ++r)
                        St[(cA + c) * ST_PITCH + i0 + r] = acc[r][c];
            }
        }
        __syncthreads();

        const int rglob = 32 * qb + row;
        const int sbeg  = 32 * p;
        float lmax = -3.0e38f;
        if (sbeg < ncols) {
            int send = min(sbeg + 32, rglob + 1);
            for (int s = sbeg; s < send; ++s)
                lmax = fmaxf(lmax, St[s * ST_PITCH + row]);
        }
        red[p * 32 + row] = lmax;
        __syncthreads();
        if (p == 0) {
            float m = red[row];
            #pragma unroll
            for (int q = 1; q < 8; ++q) m = fmaxf(m, red[q * 32 + row]);
            rmax[row] = m;
        }
        __syncthreads();
        const float m = rmax[row];
        float lsum = 0.0f;
        if (sbeg < ncols) {
            #pragma unroll 4
            for (int s = sbeg; s < sbeg + 32; ++s) {
                float sv = St[s * ST_PITCH + row];
                float pv = (s <= rglob) ? __expf(sv - m) : 0.0f;
                St[s * ST_PITCH + row] = pv;
                lsum += pv;
            }
        }
        red[p * 32 + row] = lsum;
        __syncthreads();
        if (p == 0) {
            float ssum = red[row];
            #pragma unroll
            for (int q = 1; q < 8; ++q) ssum += red[q * 32 + row];
            rsum[row] = 1.0f / ssum;
        }
        __syncthreads();

        float oacc[4][2];
        #pragma unroll
        for (int r = 0; r < 4; ++r) { oacc[r][0] = 0.0f; oacc[r][1] = 0.0f; }
        #pragma unroll 8
        for (int s = 0; s < ncols; ++s) {
            float4 a = *reinterpret_cast<const float4*>(&St[s * ST_PITCH + i0v]);
            float2 b = *reinterpret_cast<const float2*>(&Vs[s * H_ + c0v]);
            float av[4] = {a.x, a.y, a.z, a.w};
            #pragma unroll
            for (int r = 0; r < 4; ++r) {
                oacc[r][0] = fmaf(av[r], b.x, oacc[r][0]);
                oacc[r][1] = fmaf(av[r], b.y, oacc[r][1]);
            }
        }
        #pragma unroll
        for (int r = 0; r < 4; ++r) {
            float inv = rsum[i0v + r];
            float2 o;
            o.x = oacc[r][0] * inv;
            o.y = oacc[r][1] * inv;
            *reinterpret_cast<float2*>(
                &out[((size_t)bb * T_ + 32 * qb + i0v + r) * H_ + c0v]) = o;
        }
    }
}

// ---------------------------------------------------------------------------
extern "C" void kernel_launch(void* const* d_in, const int* in_sizes, int n_in,
                              void* d_out, int out_size) {
    const float* x  = (const float*)d_in[0];
    const float* Wq = (const float*)d_in[1];
    const float* Wk = (const float*)d_in[2];
    const float* Wv = (const float*)d_in[3];
    float* out = (float*)d_out;

    cudaFuncSetAttribute(proj_mma_kernel, cudaFuncAttributeMaxDynamicSharedMemorySize, PROJ_SMEM);
    cudaFuncSetAttribute(attn_kernel, cudaFuncAttributeMaxDynamicSharedMemorySize, ATTN_SMEM);

    proj_mma_kernel<<<(B_ * T_) / 128, 256, PROJ_SMEM>>>(x, Wq, Wk, Wv);
    attn_kernel<<<B_, 256, ATTN_SMEM>>>(out);
}

// round 4
// speedup vs baseline: 2.4753x; 1.9324x over previous
#include <cuda_runtime.h>
#include <cuda_bf16.h>
#include <cstdint>

#define B_ 512
#define T_ 256
#define C_ 384
#define H_ 64
#define SCALE_F 19.595917942265423f

// scratch: q,k,v projections [B,T,H] fp32
__device__ float g_q[B_ * T_ * H_];
__device__ float g_k[B_ * T_ * H_];
__device__ float g_v[B_ * T_ * H_];
// W in fragment-linear layout: [half(2)][chunk(6)][hl(2)][nt(12)][ks(4)][lane(32)][reg(2)] b32
__device__ uint32_t g_Wfrag32[73728];

__device__ __forceinline__ uint32_t smem_u32(const void* p) {
    uint32_t a;
    asm("{ .reg .u64 t; cvta.to.shared.u64 t, %1; cvt.u32.u64 %0, t; }"
        : "=r"(a) : "l"(p));
    return a;
}
#define CP_ASYNC16(dst_u32, src_ptr) \
    asm volatile("cp.async.ca.shared.global [%0], [%1], 16;" \
                 :: "r"(dst_u32), "l"(src_ptr) : "memory")
#define CP_COMMIT()  asm volatile("cp.async.commit_group;" ::: "memory")
#define CP_WAIT0()   asm volatile("cp.async.wait_group 0;" ::: "memory")

__device__ __forceinline__ void hmma_bf16(float* c, const uint32_t* a, const uint32_t* b) {
    asm volatile("mma.sync.aligned.m16n8k16.row.col.f32.bf16.bf16.f32 "
        "{%0,%1,%2,%3},{%4,%5,%6,%7},{%8,%9},{%0,%1,%2,%3};"
        : "+f"(c[0]), "+f"(c[1]), "+f"(c[2]), "+f"(c[3])
        : "r"(a[0]), "r"(a[1]), "r"(a[2]), "r"(a[3]), "r"(b[0]), "r"(b[1]));
}

// ======================= W split to fragment layout =======================
// element (n=mat*64+col, k): bf16 hi/lo pairs packed per mma B-fragment slot.
__global__ void split_w_kernel(const float* __restrict__ Wq,
                               const float* __restrict__ Wk,
                               const float* __restrict__ Wv) {
    int t = blockIdx.x * 256 + threadIdx.x;   // 36864 = 192 n x 192 k-pairs
    if (t >= 192 * 192) return;
    int n  = t / 192;
    int kp = t - n * 192;
    int k0 = kp * 2;
    int mat = n >> 6, col = n & 63;
    const float* W = (mat == 0) ? Wq : (mat == 1 ? Wk : Wv);
    float v0 = W[(size_t)k0 * 64 + col];
    float v1 = W[(size_t)(k0 + 1) * 64 + col];
    __nv_bfloat16 h0 = __float2bfloat16(v0);
    __nv_bfloat16 h1 = __float2bfloat16(v1);
    __nv_bfloat16 l0 = __float2bfloat16(v0 - __bfloat162float(h0));
    __nv_bfloat16 l1 = __float2bfloat16(v1 - __bfloat162float(h1));
    __nv_bfloat162 hp = __halves2bfloat162(h0, h1);
    __nv_bfloat162 lp = __halves2bfloat162(l0, l1);

    int half  = (n >= 96) ? 1 : 0;
    int nl    = n - 96 * half;
    int nt    = nl >> 3;
    int chunk = k0 >> 6;
    int kc    = k0 & 63;
    int ks    = kc >> 4;
    int kk    = kc & 15;
    int lane  = ((nl & 7) << 2) | ((kk >> 1) & 3);
    int reg   = kk >> 3;
    int idx0 = (((((half * 6 + chunk) * 2 + 0) * 12 + nt) * 4 + ks) * 32 + lane) * 2 + reg;
    int idx1 = (((((half * 6 + chunk) * 2 + 1) * 12 + nt) * 4 + ks) * 32 + lane) * 2 + reg;
    g_Wfrag32[idx0] = *reinterpret_cast<uint32_t*>(&hp);
    g_Wfrag32[idx1] = *reinterpret_cast<uint32_t*>(&lp);
}

// ======================= projection (bf16 mma.sync) =======================
// CTA tile M=128 x N=96, K chunks of 64 (6 chunks), 3-pass split.
// smem (b32): sA [hl(2)][mt(8)][ks(4)][lane(32)][reg(4)] = 8192
//             sB [hl(2)][nt(12)][ks(4)][lane(32)][reg(2)] = 6144
#define SA_B32 8192
#define SB_B32 6144
#define PROJ_SMEM ((SA_B32 + SB_B32) * 4)    // 57344 B

__global__ __launch_bounds__(256, 2)
void proj_bf16_kernel(const float* __restrict__ x) {
    extern __shared__ uint32_t sm32[];
    uint32_t* sA = sm32;
    uint32_t* sB = sm32 + SA_B32;
    const uint32_t sB_smem = smem_u32(sB);

    const int tid  = threadIdx.x;
    const int lane = tid & 31;
    const int wid  = tid >> 5;
    const int wm   = wid >> 2;                // 0..1 : 64 M-rows
    const int wn   = wid & 3;                 // 0..3 : 24 N-cols
    const int mtile = blockIdx.x >> 1;
    const int half  = blockIdx.x & 1;
    const int row0  = mtile * 128;

    float acc[4][3][4];
    #pragma unroll
    for (int mt = 0; mt < 4; ++mt)
        #pragma unroll
        for (int nt = 0; nt < 3; ++nt)
            #pragma unroll
            for (int e = 0; e < 4; ++e) acc[mt][nt][e] = 0.0f;

    #pragma unroll 1
    for (int c = 0; c < 6; ++c) {
        __syncthreads();                      // previous mma done reading smem

        // ---- B: pure async copy of prearranged fragments (24 KB) ----
        {
            const uint32_t* src = g_Wfrag32 + (size_t)(half * 6 + c) * SB_B32;
            #pragma unroll
            for (int j = 0; j < 6; ++j) {
                int i = tid + j * 256;        // 0..1535 (x16B)
                CP_ASYNC16(sB_smem + i * 16, src + i * 4);
            }
            CP_COMMIT();
        }

        // ---- A: load x, split to bf16 hi/lo, store in fragment order ----
        #pragma unroll
        for (int j = 0; j < 8; ++j) {
            int idx = tid + j * 256;          // 0..2047 = 128 m x 16 float4
            int m  = idx >> 4;
            int c4 = idx & 15;
            float4 v = *reinterpret_cast<const float4*>(
                x + (size_t)(row0 + m) * C_ + c * 64 + c4 * 4);
            __nv_bfloat16 h0 = __float2bfloat16(v.x);
            __nv_bfloat16 h1 = __float2bfloat16(v.y);
            __nv_bfloat16 h2 = __float2bfloat16(v.z);
            __nv_bfloat16 h3 = __float2bfloat16(v.w);
            __nv_bfloat16 l0 = __float2bfloat16(v.x - __bfloat162float(h0));
            __nv_bfloat16 l1 = __float2bfloat16(v.y - __bfloat162float(h1));
            __nv_bfloat16 l2 = __float2bfloat16(v.z - __bfloat162float(h2));
            __nv_bfloat16 l3 = __float2bfloat16(v.w - __bfloat162float(h3));
            __nv_bfloat162 hp0 = __halves2bfloat162(h0, h1);
            __nv_bfloat162 hp1 = __halves2bfloat162(h2, h3);
            __nv_bfloat162 lp0 = __halves2bfloat162(l0, l1);
            __nv_bfloat162 lp1 = __halves2bfloat162(l2, l3);
            int mt    = m >> 4;
            int ks    = c4 >> 2;
            int lane0 = ((m & 7) << 2) | (2 * (c4 & 1));
            int reg   = (c4 & 2) | ((m & 8) >> 3);
            int b0 = ((mt * 4 + ks) * 32 + lane0) * 4 + reg;       // hl=0
            sA[b0]                 = *reinterpret_cast<uint32_t*>(&hp0);
            sA[b0 + 4]             = *reinterpret_cast<uint32_t*>(&hp1);   // lane0+1
            sA[b0 + SA_B32 / 2]     = *reinterpret_cast<uint32_t*>(&lp0);  // hl=1
            sA[b0 + SA_B32 / 2 + 4] = *reinterpret_cast<uint32_t*>(&lp1);
        }
        CP_WAIT0();
        __syncthreads();

        // ---- MMA over chunk ----
        #pragma unroll
        for (int ks = 0; ks < 4; ++ks) {
            uint32_t af[2][4][4];
            uint32_t bf[2][3][2];
            #pragma unroll
            for (int hl = 0; hl < 2; ++hl)
                #pragma unroll
                for (int mt = 0; mt < 4; ++mt) {
                    const uint32_t* p = sA + ((((hl * 8) + wm * 4 + mt) * 4 + ks) * 32 + lane) * 4;
                    uint4 q = *reinterpret_cast<const uint4*>(p);
                    af[hl][mt][0] = q.x; af[hl][mt][1] = q.y;
                    af[hl][mt][2] = q.z; af[hl][mt][3] = q.w;
                }
            #pragma unroll
            for (int hl = 0; hl < 2; ++hl)
                #pragma unroll
                for (int nt = 0; nt < 3; ++nt) {
                    const uint32_t* p = sB + ((((hl * 12) + wn * 3 + nt) * 4 + ks) * 32 + lane) * 2;
                    uint2 q = *reinterpret_cast<const uint2*>(p);
                    bf[hl][nt][0] = q.x; bf[hl][nt][1] = q.y;
                }
            #pragma unroll
            for (int mt = 0; mt < 4; ++mt)
                #pragma unroll
                for (int nt = 0; nt < 3; ++nt)
                    hmma_bf16(acc[mt][nt], af[0][mt], bf[0][nt]);   // hi*hi
            #pragma unroll
            for (int mt = 0; mt < 4; ++mt)
                #pragma unroll
                for (int nt = 0; nt < 3; ++nt)
                    hmma_bf16(acc[mt][nt], af[0][mt], bf[1][nt]);   // hi*lo
            #pragma unroll
            for (int mt = 0; mt < 4; ++mt)
                #pragma unroll
                for (int nt = 0; nt < 3; ++nt)
                    hmma_bf16(acc[mt][nt], af[1][mt], bf[0][nt]);   // lo*hi
        }
    }

    // ---- epilogue: write q/k/v ----
    #pragma unroll
    for (int mt = 0; mt < 4; ++mt) {
        #pragma unroll
        for (int nt = 0; nt < 3; ++nt) {
            int n0  = half * 96 + wn * 24 + nt * 8;
            int mat = n0 >> 6;
            int col = (n0 & 63) + (lane & 3) * 2;
            float* O = (mat == 0) ? g_q : (mat == 1 ? g_k : g_v);
            int grow = row0 + wm * 64 + mt * 16 + (lane >> 2);
            *reinterpret_cast<float2*>(&O[(size_t)grow * 64 + col]) =
                make_float2(acc[mt][nt][0], acc[mt][nt][1]);
            *reinterpret_cast<float2*>(&O[(size_t)(grow + 8) * 64 + col]) =
                make_float2(acc[mt][nt][2], acc[mt][nt][3]);
        }
    }
}

// ---------------------------------------------------------------------------
// Attention kernel: one CTA per batch. (unchanged — known good)
// ---------------------------------------------------------------------------
#define KT_PITCH 260
#define QT_PITCH 36
#define ST_PITCH 36
#define ATTN_SMEM ((64 * KT_PITCH + T_ * H_ + 64 * QT_PITCH + T_ * ST_PITCH + 256 + 32 + 32) * 4)

__global__ __launch_bounds__(256, 1)
void attn_kernel(float* __restrict__ out) {
    extern __shared__ float sm[];
    float* Kt   = sm;
    float* Vs   = Kt + 64 * KT_PITCH;
    float* Qt   = Vs + T_ * H_;
    float* St   = Qt + 64 * QT_PITCH;
    float* red  = St + T_ * ST_PITCH;
    float* rmax = red + 256;
    float* rsum = rmax + 32;

    const int bb  = blockIdx.x;
    const int tid = threadIdx.x;
    const float* qp = g_q + (size_t)bb * T_ * H_;
    const float* kp = g_k + (size_t)bb * T_ * H_;
    const float* vp = g_v + (size_t)bb * T_ * H_;

    #pragma unroll 4
    for (int it = 0; it < 64; ++it) {
        int idx = tid + it * 256;
        int s = idx >> 6, h = idx & 63;
        Kt[h * KT_PITCH + s] = kp[idx];
        Vs[idx] = vp[idx];
    }

    const int rg  = tid & 7;
    const int i0  = rg * 4;
    const int cg  = tid >> 3;
    const int cA  = cg * 4;
    const int cB  = 128 + cg * 4;
    const int p   = tid >> 5;
    const int row = tid & 31;
    const int i0v = (tid >> 5) * 4;
    const int c0v = (tid & 31) * 2;

    #pragma unroll 1
    for (int qb = 0; qb < 8; ++qb) {
        const int ncols = 32 * (qb + 1);

        __syncthreads();
        #pragma unroll
        for (int it = 0; it < 8; ++it) {
            int idx = tid + it * 256;
            int i = idx >> 6, h = idx & 63;
            Qt[h * QT_PITCH + i] = qp[(32 * qb + i) * H_ + h] * SCALE_F;
        }
        __syncthreads();

        if (cA < ncols) {
            float acc[4][8];
            #pragma unroll
            for (int r = 0; r < 4; ++r)
                #pragma unroll
                for (int c = 0; c < 8; ++c) acc[r][c] = 0.0f;

            if (cB < ncols) {
                #pragma unroll 8
                for (int k = 0; k < 64; ++k) {
                    float4 a  = *reinterpret_cast<const float4*>(&Qt[k * QT_PITCH + i0]);
                    float4 b0 = *reinterpret_cast<const float4*>(&Kt[k * KT_PITCH + cA]);
                    float4 b1 = *reinterpret_cast<const float4*>(&Kt[k * KT_PITCH + cB]);
                    float av[4] = {a.x, a.y, a.z, a.w};
                    float b0v[4] = {b0.x, b0.y, b0.z, b0.w};
                    float b1v[4] = {b1.x, b1.y, b1.z, b1.w};
                    #pragma unroll
                    for (int r = 0; r < 4; ++r) {
                        #pragma unroll
                        for (int c = 0; c < 4; ++c) {
                            acc[r][c]     = fmaf(av[r], b0v[c], acc[r][c]);
                            acc[r][c + 4] = fmaf(av[r], b1v[c], acc[r][c + 4]);
                        }
                    }
                }
                #pragma unroll
                for (int c = 0; c < 4; ++c)
                    #pragma unroll
                    for (int r = 0; r < 4; ++r) {
                        St[(cA + c) * ST_PITCH + i0 + r] = acc[r][c];
                        St[(cB + c) * ST_PITCH + i0 + r] = acc[r][c + 4];
                    }
            } else {
                #pragma unroll 8
                for (int k = 0; k < 64; ++k) {
                    float4 a  = *reinterpret_cast<const float4*>(&Qt[k * QT_PITCH + i0]);
                    float4 b0 = *reinterpret_cast<const float4*>(&Kt[k * KT_PITCH + cA]);
                    float av[4] = {a.x, a.y, a.z, a.w};
                    float b0v[4] = {b0.x, b0.y, b0.z, b0.w};
                    #pragma unroll
                    for (int r = 0; r < 4; ++r)
                        #pragma unroll
                        for (int c = 0; c < 4; ++c)
                            acc[r][c] = fmaf(av[r], b0v[c], acc[r][c]);
                }
                #pragma unroll
                for (int c = 0; c < 4; ++c)
                    #pragma unroll
                    for (int r = 0; r < 4; ++r)
                        St[(cA + c) * ST_PITCH + i0 + r] = acc[r][c];
            }
        }
        __syncthreads();

        const int rglob = 32 * qb + row;
        const int sbeg  = 32 * p;
        float lmax = -3.0e38f;
        if (sbeg < ncols) {
            int send = min(sbeg + 32, rglob + 1);
            for (int s = sbeg; s < send; ++s)
                lmax = fmaxf(lmax, St[s * ST_PITCH + row]);
        }
        red[p * 32 + row] = lmax;
        __syncthreads();
        if (p == 0) {
            float m = red[row];
            #pragma unroll
            for (int q = 1; q < 8; ++q) m = fmaxf(m, red[q * 32 + row]);
            rmax[row] = m;
        }
        __syncthreads();
        const float m = rmax[row];
        float lsum = 0.0f;
        if (sbeg < ncols) {
            #pragma unroll 4
            for (int s = sbeg; s < sbeg + 32; ++s) {
                float sv = St[s * ST_PITCH + row];
                float pv = (s <= rglob) ? __expf(sv - m) : 0.0f;
                St[s * ST_PITCH + row] = pv;
                lsum += pv;
            }
        }
        red[p * 32 + row] = lsum;
        __syncthreads();
        if (p == 0) {
            float ssum = red[row];
            #pragma unroll
            for (int q = 1; q < 8; ++q) ssum += red[q * 32 + row];
            rsum[row] = 1.0f / ssum;
        }
        __syncthreads();

        float oacc[4][2];
        #pragma unroll
        for (int r = 0; r < 4; ++r) { oacc[r][0] = 0.0f; oacc[r][1] = 0.0f; }
        #pragma unroll 8
        for (int s = 0; s < ncols; ++s) {
            float4 a = *reinterpret_cast<const float4*>(&St[s * ST_PITCH + i0v]);
            float2 b = *reinterpret_cast<const float2*>(&Vs[s * H_ + c0v]);
            float av[4] = {a.x, a.y, a.z, a.w};
            #pragma unroll
            for (int r = 0; r < 4; ++r) {
                oacc[r][0] = fmaf(av[r], b.x, oacc[r][0]);
                oacc[r][1] = fmaf(av[r], b.y, oacc[r][1]);
            }
        }
        #pragma unroll
        for (int r = 0; r < 4; ++r) {
            float inv = rsum[i0v + r];
            float2 o;
            o.x = oacc[r][0] * inv;
            o.y = oacc[r][1] * inv;
            *reinterpret_cast<float2*>(
                &out[((size_t)bb * T_ + 32 * qb + i0v + r) * H_ + c0v]) = o;
        }
    }
}

// ---------------------------------------------------------------------------
extern "C" void kernel_launch(void* const* d_in, const int* in_sizes, int n_in,
                              void* d_out, int out_size) {
    const float* x  = (const float*)d_in[0];
    const float* Wq = (const float*)d_in[1];
    const float* Wk = (const float*)d_in[2];
    const float* Wv = (const float*)d_in[3];
    float* out = (float*)d_out;

    cudaFuncSetAttribute(proj_bf16_kernel, cudaFuncAttributeMaxDynamicSharedMemorySize, PROJ_SMEM);
    cudaFuncSetAttribute(attn_kernel, cudaFuncAttributeMaxDynamicSharedMemorySize, ATTN_SMEM);

    split_w_kernel<<<144, 256>>>(Wq, Wk, Wv);
    proj_bf16_kernel<<<2048, 256, PROJ_SMEM>>>(x);
    attn_kernel<<<B_, 256, ATTN_SMEM>>>(out);
}

// round 5
// speedup vs baseline: 4.1543x; 1.6783x over previous
#include <cuda_runtime.h>
#include <cuda_bf16.h>
#include <cstdint>

#define B_ 512
#define T_ 256
#define C_ 384
#define H_ 64
#define SCALE_F 19.595917942265423f
#define QK_SCALE (SCALE_F * 1.4426950408889634f)   // fold log2(e) -> use ex2

// scratch: q,k,v projections [B,T,H] fp32
__device__ float g_q[B_ * T_ * H_];
__device__ float g_k[B_ * T_ * H_];
__device__ float g_v[B_ * T_ * H_];
// W in fragment-linear layout: [half(2)][chunk(6)][hl(2)][nt(12)][ks(4)][lane(32)][reg(2)] b32
__device__ uint32_t g_Wfrag32[73728];

__device__ __forceinline__ uint32_t smem_u32(const void* p) {
    uint32_t a;
    asm("{ .reg .u64 t; cvta.to.shared.u64 t, %1; cvt.u32.u64 %0, t; }"
        : "=r"(a) : "l"(p));
    return a;
}
#define CP_ASYNC16(dst_u32, src_ptr) \
    asm volatile("cp.async.ca.shared.global [%0], [%1], 16;" \
                 :: "r"(dst_u32), "l"(src_ptr) : "memory")
#define CP_COMMIT()  asm volatile("cp.async.commit_group;" ::: "memory")
#define CP_WAIT0()   asm volatile("cp.async.wait_group 0;" ::: "memory")

__device__ __forceinline__ void hmma_bf16(float* c, const uint32_t* a, const uint32_t* b) {
    asm volatile("mma.sync.aligned.m16n8k16.row.col.f32.bf16.bf16.f32 "
        "{%0,%1,%2,%3},{%4,%5,%6,%7},{%8,%9},{%0,%1,%2,%3};"
        : "+f"(c[0]), "+f"(c[1]), "+f"(c[2]), "+f"(c[3])
        : "r"(a[0]), "r"(a[1]), "r"(a[2]), "r"(a[3]), "r"(b[0]), "r"(b[1]));
}
__device__ __forceinline__ float ex2f(float x) {
    float y;
    asm("ex2.approx.f32 %0, %1;" : "=f"(y) : "f"(x));
    return y;
}
__device__ __forceinline__ void pack_hl(float x, float y, uint32_t& hi, uint32_t& lo) {
    __nv_bfloat16 hx = __float2bfloat16(x), hy = __float2bfloat16(y);
    __nv_bfloat16 lx = __float2bfloat16(x - __bfloat162float(hx));
    __nv_bfloat16 ly = __float2bfloat16(y - __bfloat162float(hy));
    __nv_bfloat162 h = __halves2bfloat162(hx, hy);
    __nv_bfloat162 l = __halves2bfloat162(lx, ly);
    hi = *reinterpret_cast<uint32_t*>(&h);
    lo = *reinterpret_cast<uint32_t*>(&l);
}

// ======================= W split to fragment layout =======================
__global__ void split_w_kernel(const float* __restrict__ Wq,
                               const float* __restrict__ Wk,
                               const float* __restrict__ Wv) {
    int t = blockIdx.x * 256 + threadIdx.x;   // 36864 = 192 n x 192 k-pairs
    if (t >= 192 * 192) return;
    int n  = t / 192;
    int kp = t - n * 192;
    int k0 = kp * 2;
    int mat = n >> 6, col = n & 63;
    const float* W = (mat == 0) ? Wq : (mat == 1 ? Wk : Wv);
    float v0 = W[(size_t)k0 * 64 + col];
    float v1 = W[(size_t)(k0 + 1) * 64 + col];
    uint32_t hp, lp;
    pack_hl(v0, v1, hp, lp);

    int half  = (n >= 96) ? 1 : 0;
    int nl    = n - 96 * half;
    int nt    = nl >> 3;
    int chunk = k0 >> 6;
    int kc    = k0 & 63;
    int ks    = kc >> 4;
    int kk    = kc & 15;
    int lane  = ((nl & 7) << 2) | ((kk >> 1) & 3);
    int reg   = kk >> 3;
    int idx0 = (((((half * 6 + chunk) * 2 + 0) * 12 + nt) * 4 + ks) * 32 + lane) * 2 + reg;
    int idx1 = (((((half * 6 + chunk) * 2 + 1) * 12 + nt) * 4 + ks) * 32 + lane) * 2 + reg;
    g_Wfrag32[idx0] = hp;
    g_Wfrag32[idx1] = lp;
}

// ======================= projection (bf16 mma.sync) =======================
#define SA_B32 8192
#define SB_B32 6144
#define PROJ_SMEM ((SA_B32 + SB_B32) * 4)    // 57344 B

__global__ __launch_bounds__(256, 2)
void proj_bf16_kernel(const float* __restrict__ x) {
    extern __shared__ uint32_t sm32[];
    uint32_t* sA = sm32;
    uint32_t* sB = sm32 + SA_B32;
    const uint32_t sB_smem = smem_u32(sB);

    const int tid  = threadIdx.x;
    const int lane = tid & 31;
    const int wid  = tid >> 5;
    const int wm   = wid >> 2;
    const int wn   = wid & 3;
    const int mtile = blockIdx.x >> 1;
    const int half  = blockIdx.x & 1;
    const int row0  = mtile * 128;

    float acc[4][3][4];
    #pragma unroll
    for (int mt = 0; mt < 4; ++mt)
        #pragma unroll
        for (int nt = 0; nt < 3; ++nt)
            #pragma unroll
            for (int e = 0; e < 4; ++e) acc[mt][nt][e] = 0.0f;

    #pragma unroll 1
    for (int c = 0; c < 6; ++c) {
        __syncthreads();
        {
            const uint32_t* src = g_Wfrag32 + (size_t)(half * 6 + c) * SB_B32;
            #pragma unroll
            for (int j = 0; j < 6; ++j) {
                int i = tid + j * 256;
                CP_ASYNC16(sB_smem + i * 16, src + i * 4);
            }
            CP_COMMIT();
        }
        #pragma unroll
        for (int j = 0; j < 8; ++j) {
            int idx = tid + j * 256;
            int m  = idx >> 4;
            int c4 = idx & 15;
            float4 v = *reinterpret_cast<const float4*>(
                x + (size_t)(row0 + m) * C_ + c * 64 + c4 * 4);
            uint32_t hp0, lp0, hp1, lp1;
            pack_hl(v.x, v.y, hp0, lp0);
            pack_hl(v.z, v.w, hp1, lp1);
            int mt    = m >> 4;
            int ks    = c4 >> 2;
            int lane0 = ((m & 7) << 2) | (2 * (c4 & 1));
            int reg   = (c4 & 2) | ((m & 8) >> 3);
            int b0 = ((mt * 4 + ks) * 32 + lane0) * 4 + reg;
            sA[b0]                  = hp0;
            sA[b0 + 4]              = hp1;
            sA[b0 + SA_B32 / 2]     = lp0;
            sA[b0 + SA_B32 / 2 + 4] = lp1;
        }
        CP_WAIT0();
        __syncthreads();

        #pragma unroll
        for (int ks = 0; ks < 4; ++ks) {
            uint32_t af[2][4][4];
            uint32_t bf[2][3][2];
            #pragma unroll
            for (int hl = 0; hl < 2; ++hl)
                #pragma unroll
                for (int mt = 0; mt < 4; ++mt) {
                    const uint32_t* p = sA + ((((hl * 8) + wm * 4 + mt) * 4 + ks) * 32 + lane) * 4;
                    uint4 q = *reinterpret_cast<const uint4*>(p);
                    af[hl][mt][0] = q.x; af[hl][mt][1] = q.y;
                    af[hl][mt][2] = q.z; af[hl][mt][3] = q.w;
                }
            #pragma unroll
            for (int hl = 0; hl < 2; ++hl)
                #pragma unroll
                for (int nt = 0; nt < 3; ++nt) {
                    const uint32_t* p = sB + ((((hl * 12) + wn * 3 + nt) * 4 + ks) * 32 + lane) * 2;
                    uint2 q = *reinterpret_cast<const uint2*>(p);
                    bf[hl][nt][0] = q.x; bf[hl][nt][1] = q.y;
                }
            #pragma unroll
            for (int mt = 0; mt < 4; ++mt)
                #pragma unroll
                for (int nt = 0; nt < 3; ++nt)
                    hmma_bf16(acc[mt][nt], af[0][mt], bf[0][nt]);
            #pragma unroll
            for (int mt = 0; mt < 4; ++mt)
                #pragma unroll
                for (int nt = 0; nt < 3; ++nt)
                    hmma_bf16(acc[mt][nt], af[0][mt], bf[1][nt]);
            #pragma unroll
            for (int mt = 0; mt < 4; ++mt)
                #pragma unroll
                for (int nt = 0; nt < 3; ++nt)
                    hmma_bf16(acc[mt][nt], af[1][mt], bf[0][nt]);
        }
    }

    #pragma unroll
    for (int mt = 0; mt < 4; ++mt) {
        #pragma unroll
        for (int nt = 0; nt < 3; ++nt) {
            int n0  = half * 96 + wn * 24 + nt * 8;
            int mat = n0 >> 6;
            int col = (n0 & 63) + (lane & 3) * 2;
            float* O = (mat == 0) ? g_q : (mat == 1 ? g_k : g_v);
            int grow = row0 + wm * 64 + mt * 16 + (lane >> 2);
            *reinterpret_cast<float2*>(&O[(size_t)grow * 64 + col]) =
                make_float2(acc[mt][nt][0], acc[mt][nt][1]);
            *reinterpret_cast<float2*>(&O[(size_t)(grow + 8) * 64 + col]) =
                make_float2(acc[mt][nt][2], acc[mt][nt][3]);
        }
    }
}

// ======================= attention (bf16 mma.sync, flash-style) ===========
// One CTA per batch, 8 warps. K/V in smem as hi/lo bf16 B-fragments.
// Warp w owns m16 row-tiles {w, 15-w}: causal load perfectly balanced (5 kv
// blocks of 64 each). Online softmax in registers; C-frag -> A-frag repack.
// smem: sKhi/sKlo/sVhi/sVlo: [j(4)][ks(4)][nt(8)] x [lane(32)][reg(2)] b32
#define ATT_FRAG_B32 8192
#define ATTN_SMEM (4 * ATT_FRAG_B32 * 4)     // 131072 B

__global__ __launch_bounds__(256, 1)
void attn_mma_kernel(float* __restrict__ out) {
    extern __shared__ uint32_t am32[];
    uint32_t* sKhi = am32;
    uint32_t* sKlo = am32 + ATT_FRAG_B32;
    uint32_t* sVhi = am32 + 2 * ATT_FRAG_B32;
    uint32_t* sVlo = am32 + 3 * ATT_FRAG_B32;

    const int bb   = blockIdx.x;
    const int tid  = threadIdx.x;
    const int lane = tid & 31;
    const int w    = tid >> 5;
    const float* qp = g_q + (size_t)bb * T_ * H_;
    const float* kp = g_k + (size_t)bb * T_ * H_;
    const float* vp = g_v + (size_t)bb * T_ * H_;
    float* outp = out + (size_t)bb * T_ * H_;

    // ---- prep: convert K,V to hi/lo bf16 fragment layout ----
    #pragma unroll 4
    for (int it = 0; it < 32; ++it) {
        int slot = w + it * 8;                 // 0..255 = [j4][ks4][nt8][reg2]
        int reg = slot & 1, nt = (slot >> 1) & 7, ks = (slot >> 4) & 3, j = slot >> 6;
        int addr = (slot >> 1) * 64 + lane * 2 + reg;
        {   // K: n = key pos, k = h
            int s = j * 64 + nt * 8 + (lane >> 2);
            int h = ks * 16 + (lane & 3) * 2 + reg * 8;
            float2 kv = *reinterpret_cast<const float2*>(kp + s * 64 + h);
            uint32_t hp, lp;
            pack_hl(kv.x, kv.y, hp, lp);
            sKhi[addr] = hp; sKlo[addr] = lp;
        }
        {   // V: n = head col, k = key pos within block
            int n  = nt * 8 + (lane >> 2);
            int s0 = j * 64 + ks * 16 + (lane & 3) * 2 + reg * 8;
            float v0 = vp[s0 * 64 + n];
            float v1 = vp[(s0 + 1) * 64 + n];
            uint32_t hp, lp;
            pack_hl(v0, v1, hp, lp);
            sVhi[addr] = hp; sVlo[addr] = lp;
        }
    }
    __syncthreads();

    #pragma unroll 1
    for (int hf = 0; hf < 2; ++hf) {
        const int t = hf ? (15 - w) : w;
        const int jmax = t >> 2;
        const int r0 = t * 16 + (lane >> 2);

        // ---- load Q tile fragments (pre-scaled by SCALE*log2e), hi/lo ----
        uint32_t qh[4][4], ql[4][4];
        #pragma unroll
        for (int ks = 0; ks < 4; ++ks) {
            int k0 = ks * 16 + (lane & 3) * 2;
            float2 v00 = *reinterpret_cast<const float2*>(qp + r0 * 64 + k0);
            float2 v10 = *reinterpret_cast<const float2*>(qp + (r0 + 8) * 64 + k0);
            float2 v01 = *reinterpret_cast<const float2*>(qp + r0 * 64 + k0 + 8);
            float2 v11 = *reinterpret_cast<const float2*>(qp + (r0 + 8) * 64 + k0 + 8);
            pack_hl(v00.x * QK_SCALE, v00.y * QK_SCALE, qh[ks][0], ql[ks][0]);
            pack_hl(v10.x * QK_SCALE, v10.y * QK_SCALE, qh[ks][1], ql[ks][1]);
            pack_hl(v01.x * QK_SCALE, v01.y * QK_SCALE, qh[ks][2], ql[ks][2]);
            pack_hl(v11.x * QK_SCALE, v11.y * QK_SCALE, qh[ks][3], ql[ks][3]);
        }

        float o[8][4];
        #pragma unroll
        for (int nt = 0; nt < 8; ++nt)
            #pragma unroll
            for (int e = 0; e < 4; ++e) o[nt][e] = 0.0f;
        float m0 = -1.0e30f, m1 = -1.0e30f, l0 = 0.0f, l1 = 0.0f;

        #pragma unroll 1
        for (int j = 0; j <= jmax; ++j) {
            // ---- S = Q K^T (3-pass) ----
            float s[8][4];
            #pragma unroll
            for (int nt = 0; nt < 8; ++nt)
                #pragma unroll
                for (int e = 0; e < 4; ++e) s[nt][e] = 0.0f;
            #pragma unroll
            for (int ks = 0; ks < 4; ++ks) {
                const uint2* kh = reinterpret_cast<const uint2*>(sKhi) + ((j * 4 + ks) * 8) * 32 + lane;
                const uint2* kl = reinterpret_cast<const uint2*>(sKlo) + ((j * 4 + ks) * 8) * 32 + lane;
                #pragma unroll
                for (int nt = 0; nt < 8; ++nt) {
                    uint2 bh2 = kh[nt * 32], bl2 = kl[nt * 32];
                    uint32_t bh[2] = {bh2.x, bh2.y};
                    uint32_t bl[2] = {bl2.x, bl2.y};
                    hmma_bf16(s[nt], qh[ks], bh);
                    hmma_bf16(s[nt], qh[ks], bl);
                    hmma_bf16(s[nt], ql[ks], bh);
                }
            }
            // ---- causal mask on diagonal block ----
            if (j == jmax) {
                int cb = 64 * j + (lane & 3) * 2;
                #pragma unroll
                for (int nt = 0; nt < 8; ++nt) {
                    int c = cb + nt * 8;
                    if (c > r0)         s[nt][0] = -1.0e30f;
                    if (c + 1 > r0)     s[nt][1] = -1.0e30f;
                    if (c > r0 + 8)     s[nt][2] = -1.0e30f;
                    if (c + 1 > r0 + 8) s[nt][3] = -1.0e30f;
                }
            }
            // ---- online softmax (quad reductions) ----
            float bm0 = -1.0e30f, bm1 = -1.0e30f;
            #pragma unroll
            for (int nt = 0; nt < 8; ++nt) {
                bm0 = fmaxf(bm0, fmaxf(s[nt][0], s[nt][1]));
                bm1 = fmaxf(bm1, fmaxf(s[nt][2], s[nt][3]));
            }
            bm0 = fmaxf(bm0, __shfl_xor_sync(0xffffffffu, bm0, 1));
            bm0 = fmaxf(bm0, __shfl_xor_sync(0xffffffffu, bm0, 2));
            bm1 = fmaxf(bm1, __shfl_xor_sync(0xffffffffu, bm1, 1));
            bm1 = fmaxf(bm1, __shfl_xor_sync(0xffffffffu, bm1, 2));
            float mn0 = fmaxf(m0, bm0), mn1 = fmaxf(m1, bm1);
            float sc0 = ex2f(m0 - mn0), sc1 = ex2f(m1 - mn1);
            float rs0 = 0.0f, rs1 = 0.0f;
            #pragma unroll
            for (int nt = 0; nt < 8; ++nt) {
                s[nt][0] = ex2f(s[nt][0] - mn0);
                s[nt][1] = ex2f(s[nt][1] - mn0);
                s[nt][2] = ex2f(s[nt][2] - mn1);
                s[nt][3] = ex2f(s[nt][3] - mn1);
                rs0 += s[nt][0] + s[nt][1];
                rs1 += s[nt][2] + s[nt][3];
            }
            rs0 += __shfl_xor_sync(0xffffffffu, rs0, 1);
            rs0 += __shfl_xor_sync(0xffffffffu, rs0, 2);
            rs1 += __shfl_xor_sync(0xffffffffu, rs1, 1);
            rs1 += __shfl_xor_sync(0xffffffffu, rs1, 2);
            l0 = l0 * sc0 + rs0;
            l1 = l1 * sc1 + rs1;
            m0 = mn0; m1 = mn1;
            #pragma unroll
            for (int nt = 0; nt < 8; ++nt) {
                o[nt][0] *= sc0; o[nt][1] *= sc0;
                o[nt][2] *= sc1; o[nt][3] *= sc1;
            }
            // ---- O += P V (C-frag -> A-frag repack, 3-pass) ----
            #pragma unroll
            for (int kk = 0; kk < 4; ++kk) {
                uint32_t pah[4], pal[4];
                pack_hl(s[2 * kk][0],     s[2 * kk][1],     pah[0], pal[0]);
                pack_hl(s[2 * kk][2],     s[2 * kk][3],     pah[1], pal[1]);
                pack_hl(s[2 * kk + 1][0], s[2 * kk + 1][1], pah[2], pal[2]);
                pack_hl(s[2 * kk + 1][2], s[2 * kk + 1][3], pah[3], pal[3]);
                const uint2* vh = reinterpret_cast<const uint2*>(sVhi) + ((j * 4 + kk) * 8) * 32 + lane;
                const uint2* vl = reinterpret_cast<const uint2*>(sVlo) + ((j * 4 + kk) * 8) * 32 + lane;
                #pragma unroll
                for (int nt = 0; nt < 8; ++nt) {
                    uint2 bh2 = vh[nt * 32], bl2 = vl[nt * 32];
                    uint32_t bh[2] = {bh2.x, bh2.y};
                    uint32_t bl[2] = {bl2.x, bl2.y};
                    hmma_bf16(o[nt], pah, bh);
                    hmma_bf16(o[nt], pah, bl);
                    hmma_bf16(o[nt], pal, bh);
                }
            }
        }

        // ---- epilogue ----
        float inv0 = 1.0f / l0, inv1 = 1.0f / l1;
        #pragma unroll
        for (int nt = 0; nt < 8; ++nt) {
            int col = nt * 8 + (lane & 3) * 2;
            *reinterpret_cast<float2*>(outp + r0 * 64 + col) =
                make_float2(o[nt][0] * inv0, o[nt][1] * inv0);
            *reinterpret_cast<float2*>(outp + (r0 + 8) * 64 + col) =
                make_float2(o[nt][2] * inv1, o[nt][3] * inv1);
        }
    }
}

// ---------------------------------------------------------------------------
extern "C" void kernel_launch(void* const* d_in, const int* in_sizes, int n_in,
                              void* d_out, int out_size) {
    const float* x  = (const float*)d_in[0];
    const float* Wq = (const float*)d_in[1];
    const float* Wk = (const float*)d_in[2];
    const float* Wv = (const float*)d_in[3];
    float* out = (float*)d_out;

    cudaFuncSetAttribute(proj_bf16_kernel, cudaFuncAttributeMaxDynamicSharedMemorySize, PROJ_SMEM);
    cudaFuncSetAttribute(attn_mma_kernel, cudaFuncAttributeMaxDynamicSharedMemorySize, ATTN_SMEM);

    split_w_kernel<<<144, 256>>>(Wq, Wk, Wv);
    proj_bf16_kernel<<<2048, 256, PROJ_SMEM>>>(x);
    attn_mma_kernel<<<B_, 256, ATTN_SMEM>>>(out);
}